// round 12
// baseline (speedup 1.0000x reference)
#include <cuda_runtime.h>

#define NB 32
#define NA 3
#define NH 52
#define NW 52
#define NC 80
#define HW (NH*NW)                    // 2704
#define CELLS_PER_B (NA*HW)           // 8112
#define MAXB 50
#define GTPAD 52
#define CANDMAX 56
#define BLK 256
#define NWARPS (BLK/32)
#define GXB ((CELLS_PER_B + BLK - 1)/BLK)  // 32
#define NPART (GXB*NB)                // 1024
#define QMAX 64

__constant__ float c_AW[3] = {10.f/32.f, 16.f/32.f, 33.f/32.f};
__constant__ float c_AH[3] = {13.f/32.f, 30.f/32.f, 23.f/32.f};

__device__ float g_partial[NPART][3];
__device__ int   g_count = 0;

// FMA-pipe exp: magic-number round-to-nearest + deg-6 Taylor for 2^f, exponent splice.
__device__ __forceinline__ float pexp(float x) {
    float y = x * 1.4426950408889634f;
    y = fminf(fmaxf(y, -80.f), 80.f);
    float fm = y + 12582912.f;                    // 1.5*2^23
    int   i  = __float_as_int(fm) - 0x4B400000;
    float r  = fm - 12582912.f;
    float f  = y - r;                             // f in [-0.5, 0.5]
    float p  =          1.54035304e-4f;
    p = p*f + 1.33335581e-3f;
    p = p*f + 9.61812911e-3f;
    p = p*f + 5.55041087e-2f;
    p = p*f + 2.40226507e-1f;
    p = p*f + 6.93147182e-1f;
    p = p*f + 1.f;                                // 2^f
    return __int_as_float(__float_as_int(p) + (i << 23));
}

// ---------------- fully fused kernel ----------------
__global__ void __launch_bounds__(BLK) kF(const float* __restrict__ out,
                                          const float* __restrict__ target,
                                          float* __restrict__ dout) {
    __shared__ float4   sH[GTPAD];    // {3*x1, 3*x2, y1, y2} (x pre-scaled by 3)
    __shared__ float    sNga[GTPAD];  // -garea
    __shared__ float4   sC[MAXB];     // {tx, ty, tw, th}
    __shared__ float2   sD[MAXB];     // {scale, cls-as-int}
    __shared__ int      sCell[MAXB];  // target cell (-1 invalid)
    __shared__ int      s_last[BLK];  // last gt slot targeting each local cell
    __shared__ unsigned s_bal[2];
    __shared__ float    s_pm[NWARPS];
    __shared__ float4   sHc[CANDMAX]; // compacted candidate corners
    __shared__ float    sNgac[CANDMAX];
    __shared__ int      s_nc4;
    __shared__ float    s_red[3][NWARPS];
    __shared__ int      s_qcnt;
    __shared__ int      s_qoff[QMAX];
    __shared__ unsigned s_qb0[QMAX], s_qb1[QMAX], s_qb2[QMAX];
    __shared__ int      s_islast;

    int b = blockIdx.y, tid = threadIdx.x;
    int lane = tid & 31, wid = tid >> 5;
    int base = blockIdx.x*BLK;
    unsigned ltm = (1u << lane) - 1u;

    // ---- PREFETCH: issue the 5 channel loads first ----
    int idx0 = base + tid;
    bool v0 = idx0 < CELLS_PER_B;
    int i0 = v0 ? idx0 : 0;
    int a0 = i0 / HW, hw0 = i0 - a0*HW;
    int off0 = (b*255 + a0*85)*HW + hw0;
    const float* o0 = out + off0;
    float L00 = __ldg(o0 + 0*HW), L01 = __ldg(o0 + 1*HW), L02 = __ldg(o0 + 2*HW),
          L03 = __ldg(o0 + 3*HW), L04 = __ldg(o0 + 4*HW);

    // ---- phase 1: read targets, ballot validity, init s_last ----
    bool  ok = false;
    float cc = 0.f, x = 0.f, y = 0.f, w = 0.f, h = 0.f;
    if (tid < MAXB) {
        const float* tp = target + b*MAXB*5 + tid*5;
        cc = tp[0]; x = tp[1]; y = tp[2]; w = tp[3]; h = tp[4];
        ok = (x != 0.f);
    }
    if (tid < 64) {
        unsigned bal = __ballot_sync(0xffffffffu, ok);
        if (lane == 0) s_bal[wid] = bal;
    }
    s_last[tid] = -1;
    if (tid == 0) s_qcnt = 0;
    __syncthreads();

    // ---- phase 2: build gt table + scatter cell ownership ----
    if (tid < GTPAD) {
        bool valid = false;
        if (tid < MAXB) {
            if (tid < 32) {
                unsigned low = (tid == 31) ? 0xffffffffu : ((1u << (tid + 1)) - 1u);
                valid = ((s_bal[0] & low) == low);
            } else {
                unsigned low = (1u << (tid - 31)) - 1u;
                valid = (s_bal[0] == 0xffffffffu) && ((s_bal[1] & low) == low);
            }
        }
        if (valid) {
            float gx = x*(float)NW, gy = y*(float)NH;
            float gw = w*(float)NW, gh = h*(float)NH;
            int bn = 0; float best = -1e30f;
#pragma unroll
            for (int a = 0; a < 3; a++) {
                float aw = c_AW[a], ah = c_AH[a];
                float cw = fminf(0.5f*gw, 0.5f*aw) - fmaxf(-0.5f*gw, -0.5f*aw);
                float ch = fminf(0.5f*gh, 0.5f*ah) - fmaxf(-0.5f*gh, -0.5f*ah);
                float ca = (cw <= 0.f || ch <= 0.f) ? 0.f : cw*ch;
                float iou = ca / (gw*gh + aw*ah - ca);
                if (iou > best) { best = iou; bn = a; }
            }
            int gi = (int)floorf(gx), gj = (int)floorf(gy);
            int cell = bn*HW + gj*NW + gi;
            int cc_i = (int)cc; if (cc_i < 0) cc_i = 0; if (cc_i > NC-1) cc_i = NC-1;
            sH[tid]   = make_float4(3.f*(gx - 0.5f*gw), 3.f*(gx + 0.5f*gw),
                                    gy - 0.5f*gh, gy + 0.5f*gh);
            sNga[tid] = -(gw*gh);
            sC[tid]   = make_float4(gx - (float)gi, gy - (float)gj,
                                    logf(gw / c_AW[bn]), logf(gh / c_AH[bn]));
            sD[tid]   = make_float2(sqrtf(2.f - w*h), __int_as_float(cc_i));
            sCell[tid] = cell;
            int c = cell - base;
            if (c >= 0 && c < BLK) atomicMax(&s_last[c], tid);
        } else {
            sH[tid]   = make_float4(1e38f, -1e38f, 1e38f, -1e38f);
            sNga[tid] = -1e30f;                   // ga = +1e30 -> never passes prune
            if (tid < MAXB) {
                sC[tid]   = make_float4(0.f, 0.f, 0.f, 0.f);
                sD[tid]   = make_float2(0.f, __int_as_float(0));
                sCell[tid] = -1;
            }
        }
    }

    // ---- per-cell prologue (prefetched regs only; no shared reads) ----
    float s0a, s1a, paa, px1a, px2a, py1a, py2a;
    {
        float u0 = pexp(-L00), u1 = pexp(-L01);
        float d0 = 1.f + u0, d1 = 1.f + u1;
        float rr = __fdividef(1.f, d0*d1);          // single MUFU.RCP
        s0a = d1*rr; s1a = d0*rr;
        int hh = hw0 / NW, ww = hw0 - hh*NW;
        int aq = (b*3 + a0) >> 5;                   // faithful anchor-flatten quirk
        float pw = pexp(L02)*c_AW[aq], ph = pexp(L03)*c_AH[aq];
        float px = s0a + (float)ww, py = s1a + (float)hh;
        px1a = 3.f*(px - 0.5f*pw); px2a = 3.f*(px + 0.5f*pw);
        py1a = py - 0.5f*ph;       py2a = py + 0.5f*ph;
        paa = pw*ph;
    }

    // ---- block max of pred-box area (prune threshold) ----
    {
        float pm = v0 ? paa : 0.f;
#pragma unroll
        for (int off = 16; off; off >>= 1)
            pm = fmaxf(pm, __shfl_xor_sync(0xffffffffu, pm, off));
        if (lane == 0) s_pm[wid] = pm;
    }
    __syncthreads();   // covers phase-2 shared writes + s_pm

    // ---- warp 0: compact candidate gts (ga < 2*pa_max is necessary for ignore) ----
    if (wid == 0) {
        float pamax = 0.f;
#pragma unroll
        for (int j = 0; j < NWARPS; j++) pamax = fmaxf(pamax, s_pm[j]);
        float th = 2.f * pamax;
        float ng0 = sNga[lane];                      // slots 0..31
        bool  c0  = (-ng0) < th;
        bool  in1 = (lane + 32) < MAXB;              // slots 32..49
        float ng1 = in1 ? sNga[lane + 32] : -1e30f;
        bool  c1  = in1 && ((-ng1) < th);
        unsigned b0 = __ballot_sync(0xffffffffu, c0);
        unsigned b1 = __ballot_sync(0xffffffffu, c1);
        int n = __popc(b0) + __popc(b1);
        if (c0) { int p = __popc(b0 & ltm);              sHc[p] = sH[lane];      sNgac[p] = ng0; }
        if (c1) { int p = __popc(b0) + __popc(b1 & ltm); sHc[p] = sH[lane + 32]; sNgac[p] = ng1; }
        if (lane < 4) {                               // sentinel pad to next mult of 4
            sHc[n + lane]   = make_float4(1e38f, -1e38f, 1e38f, -1e38f);
            sNgac[n + lane] = -1e30f;
        }
        if (lane == 0) s_nc4 = (n + 3) >> 2;
    }
    __syncthreads();

    // ---- hot loop over compacted candidates only ----
    float dmax0 = -1e30f;
    int nc4 = s_nc4;
    for (int g4 = 0; g4 < nc4; g4++) {
#pragma unroll
        for (int j = 0; j < 4; j++) {
            float4 A  = sHc[g4*4 + j];
            float nga = sNgac[g4*4 + j];
            float cw = fmaxf(fminf(px2a, A.y) - fmaxf(px1a, A.x), 0.f);
            float ch = fmaxf(fminf(py2a, A.w) - fmaxf(py1a, A.z), 0.f);
            dmax0 = fmaxf(dmax0, fmaf(cw, ch, nga));   // 3*ca - ga
        }
    }
    bool ign0 = dmax0 > paa;       // 3*ca > pa + ga  <=>  iou > 0.5
    int last0 = s_last[tid];

    float coordL = 0.f, confL = 0.f, clsL = 0.f;

    // conf loss: merged-log.  obj: log(1+e^-c4);  back: c4 + log(1+e^-c4);  ign: 0
    {
        bool inc0 = v0 && (last0 >= 0 || !ign0);
        float t0 = inc0 ? (1.f + pexp(-L04)) : 1.f;
        if (inc0 && last0 < 0) confL += L04;
        confL += __logf(t0);
    }

    // ---- object-cell epilogue + queue append (warp-aggregated shared atomic) ----
    unsigned m0 = __ballot_sync(0xffffffffu, last0 >= 0);
    if (last0 >= 0) {
        float4 tc = sC[last0]; float m = sD[last0].x;
        float d0 = s0a*m - tc.x*m, d1 = s1a*m - tc.y*m;
        float d2 = L02*m - tc.z*m, d3 = L03*m - tc.w*m;
        coordL += 0.5f*(d0*d0 + d1*d1 + d2*d2 + d3*d3);
        unsigned cb0=0u, cb1=0u, cb2=0u;
        for (int t2 = 0; t2 < MAXB; t2++) {
            if (sCell[t2] == idx0) {
                int c = __float_as_int(sD[t2].y);
                if (c < 32)      cb0 |= 1u << c;
                else if (c < 64) cb1 |= 1u << (c - 32);
                else             cb2 |= 1u << (c - 64);
            }
        }
        int wbase = 0;
        int leader = __ffs(m0) - 1;
        if (lane == leader) wbase = atomicAdd(&s_qcnt, __popc(m0));
        wbase = __shfl_sync(m0, wbase, leader);   // mask = participating lanes ONLY
        int q = wbase + __popc(m0 & ltm);
        s_qoff[q] = off0; s_qb0[q] = cb0; s_qb1[q] = cb1; s_qb2[q] = cb2;
    }
    __syncthreads();

    // ---- warp-cooperative class loss: 80 classes over 32 lanes, merged log ----
    int qn = s_qcnt;
    for (int e = wid; e < qn; e += NWARPS) {
        int basec = s_qoff[e] + 5*HW;
        unsigned cb0 = s_qb0[e], cb1 = s_qb1[e], cb2 = s_qb2[e];
        int c0i = lane, c1i = lane + 32, c2i = lane + 64;
        bool has2 = (c2i < NC);
        float xv0 = __ldg(out + basec + c0i*HW);
        float xv1 = __ldg(out + basec + c1i*HW);
        float xv2 = has2 ? __ldg(out + basec + c2i*HW) : 0.f;
        float t0 = 1.f + pexp(-xv0);
        float t1 = 1.f + pexp(-xv1);
        float t2 = has2 ? (1.f + pexp(-xv2)) : 1.f;
        clsL += __logf(t0 * t1 * t2);               // merged: one LG2 per 3 classes
        if (!((cb0 >> c0i) & 1u)) clsL += xv0;
        if (!((cb1 >> (c1i - 32)) & 1u)) clsL += xv1;
        if (has2 && !((cb2 >> (c2i - 64)) & 1u)) clsL += xv2;
    }

    // ---- block reduce 3 sums ----
    unsigned fm = 0xffffffffu;
#pragma unroll
    for (int off = 16; off; off >>= 1) {
        coordL += __shfl_down_sync(fm, coordL, off);
        confL  += __shfl_down_sync(fm, confL,  off);
        clsL   += __shfl_down_sync(fm, clsL,   off);
    }
    if (lane == 0) { s_red[0][wid] = coordL; s_red[1][wid] = confL; s_red[2][wid] = clsL; }
    __syncthreads();
    if (tid < 3) {
        float s = 0.f;
#pragma unroll
        for (int j = 0; j < NWARPS; j++) s += s_red[tid][j];
        g_partial[blockIdx.y*gridDim.x + blockIdx.x][tid] = s;
    }
    __threadfence();
    if (tid == 0) {
        int t = atomicAdd(&g_count, 1);
        s_islast = (t == NPART - 1) ? 1 : 0;
    }
    __syncthreads();

    // ---- last block: deterministic final reduce ----
    if (s_islast) {
        volatile float* gp = &g_partial[0][0];
        float a0r = 0.f, a1r = 0.f, a2r = 0.f;
        for (int i = tid; i < NPART; i += BLK) {
            a0r += gp[i*3 + 0]; a1r += gp[i*3 + 1]; a2r += gp[i*3 + 2];
        }
#pragma unroll
        for (int off = 16; off; off >>= 1) {
            a0r += __shfl_down_sync(fm, a0r, off);
            a1r += __shfl_down_sync(fm, a1r, off);
            a2r += __shfl_down_sync(fm, a2r, off);
        }
        __shared__ float s_fin[3][NWARPS];
        if (lane == 0) { s_fin[0][wid] = a0r; s_fin[1][wid] = a1r; s_fin[2][wid] = a2r; }
        __syncthreads();
        if (tid < 3) {
            float s = 0.f;
#pragma unroll
            for (int j = 0; j < NWARPS; j++) s += s_fin[tid][j];
            dout[tid] = s / (float)NB;
        }
        if (tid == 0) g_count = 0;     // reset for next graph replay
    }
}

extern "C" void kernel_launch(void* const* d_in, const int* in_sizes, int n_in,
                              void* d_out, int out_size) {
    const float* output = (const float*)d_in[0];
    const float* target = (const float*)d_in[1];
    if (n_in >= 2 && in_sizes[0] == NB*MAXB*5) {  // defensive: inputs swapped
        output = (const float*)d_in[1];
        target = (const float*)d_in[0];
    }
    dim3 g(GXB, NB);
    kF<<<g, BLK>>>(output, target, (float*)d_out);
}

// round 13
// speedup vs baseline: 1.1514x; 1.1514x over previous
#include <cuda_runtime.h>

#define NB 32
#define NA 3
#define NH 52
#define NW 52
#define NC 80
#define HW (NH*NW)                    // 2704
#define CELLS_PER_B (NA*HW)           // 8112
#define MAXB 50
#define GTPAD 52
#define CANDMAX 56
#define BLK 256
#define NWARPS (BLK/32)
#define GXB ((CELLS_PER_B + BLK - 1)/BLK)  // 32
#define NPART (GXB*NB)                // 1024
#define QMAX 64

__constant__ float c_AW[3] = {10.f/32.f, 16.f/32.f, 33.f/32.f};
__constant__ float c_AH[3] = {13.f/32.f, 30.f/32.f, 23.f/32.f};

__device__ float g_acc[3] = {0.f, 0.f, 0.f};
__device__ int   g_count = 0;

// FMA-pipe exp: magic-number round-to-nearest + deg-6 Taylor for 2^f, exponent splice.
__device__ __forceinline__ float pexp(float x) {
    float y = x * 1.4426950408889634f;
    y = fminf(fmaxf(y, -80.f), 80.f);
    float fm = y + 12582912.f;                    // 1.5*2^23
    int   i  = __float_as_int(fm) - 0x4B400000;
    float r  = fm - 12582912.f;
    float f  = y - r;                             // f in [-0.5, 0.5]
    float p  =          1.54035304e-4f;
    p = p*f + 1.33335581e-3f;
    p = p*f + 9.61812911e-3f;
    p = p*f + 5.55041087e-2f;
    p = p*f + 2.40226507e-1f;
    p = p*f + 6.93147182e-1f;
    p = p*f + 1.f;                                // 2^f
    return __int_as_float(__float_as_int(p) + (i << 23));
}

// ---------------- fully fused kernel ----------------
__global__ void __launch_bounds__(BLK) kF(const float* __restrict__ out,
                                          const float* __restrict__ target,
                                          float* __restrict__ dout) {
    __shared__ float4   sH[GTPAD];    // {3*x1, 3*x2, y1, y2} (x pre-scaled by 3)
    __shared__ float    sNga[GTPAD];  // -garea
    __shared__ float4   sC[MAXB];     // {tx, ty, tw, th}
    __shared__ float    sM[MAXB];     // coord scale
    __shared__ int      s_last[BLK];  // last gt slot targeting each local cell
    __shared__ unsigned s_cb0[BLK], s_cb1[BLK], s_cb2[BLK];  // class-bit unions per cell
    __shared__ unsigned s_bal[2];
    __shared__ float    s_pm[NWARPS];
    __shared__ float4   sHc[CANDMAX]; // compacted candidate corners
    __shared__ float    sNgac[CANDMAX];
    __shared__ int      s_nc4;
    __shared__ float    s_red[3][NWARPS];
    __shared__ int      s_qcnt;
    __shared__ int      s_qoff[QMAX];
    __shared__ unsigned s_qb0[QMAX], s_qb1[QMAX], s_qb2[QMAX];

    int b = blockIdx.y, tid = threadIdx.x;
    int lane = tid & 31, wid = tid >> 5;
    int base = blockIdx.x*BLK;
    unsigned ltm = (1u << lane) - 1u;

    // ---- PREFETCH: issue the 5 channel loads first ----
    int idx0 = base + tid;
    bool v0 = idx0 < CELLS_PER_B;
    int i0 = v0 ? idx0 : 0;
    int a0 = i0 / HW, hw0 = i0 - a0*HW;
    int off0 = (b*255 + a0*85)*HW + hw0;
    const float* o0 = out + off0;
    float L00 = __ldg(o0 + 0*HW), L01 = __ldg(o0 + 1*HW), L02 = __ldg(o0 + 2*HW),
          L03 = __ldg(o0 + 3*HW), L04 = __ldg(o0 + 4*HW);

    // ---- phase 1: read targets, ballot validity, init shared ----
    bool  ok = false;
    float cc = 0.f, x = 0.f, y = 0.f, w = 0.f, h = 0.f;
    if (tid < MAXB) {
        const float* tp = target + b*MAXB*5 + tid*5;
        cc = tp[0]; x = tp[1]; y = tp[2]; w = tp[3]; h = tp[4];
        ok = (x != 0.f);
    }
    if (tid < 64) {
        unsigned bal = __ballot_sync(0xffffffffu, ok);
        if (lane == 0) s_bal[wid] = bal;
    }
    s_last[tid] = -1;
    s_cb0[tid] = 0u; s_cb1[tid] = 0u; s_cb2[tid] = 0u;
    if (tid == 0) s_qcnt = 0;
    __syncthreads();

    // ---- phase 2: build gt table + scatter cell ownership & class bits ----
    if (tid < GTPAD) {
        bool valid = false;
        if (tid < MAXB) {
            if (tid < 32) {
                unsigned low = (tid == 31) ? 0xffffffffu : ((1u << (tid + 1)) - 1u);
                valid = ((s_bal[0] & low) == low);
            } else {
                unsigned low = (1u << (tid - 31)) - 1u;
                valid = (s_bal[0] == 0xffffffffu) && ((s_bal[1] & low) == low);
            }
        }
        if (valid) {
            float gx = x*(float)NW, gy = y*(float)NH;
            float gw = w*(float)NW, gh = h*(float)NH;
            int bn = 0; float best = -1e30f;
#pragma unroll
            for (int a = 0; a < 3; a++) {
                float aw = c_AW[a], ah = c_AH[a];
                float cw = fminf(0.5f*gw, 0.5f*aw) - fmaxf(-0.5f*gw, -0.5f*aw);
                float ch = fminf(0.5f*gh, 0.5f*ah) - fmaxf(-0.5f*gh, -0.5f*ah);
                float ca = (cw <= 0.f || ch <= 0.f) ? 0.f : cw*ch;
                float iou = __fdividef(ca, gw*gh + aw*ah - ca);
                if (iou > best) { best = iou; bn = a; }
            }
            int gi = (int)floorf(gx), gj = (int)floorf(gy);
            int cell = bn*HW + gj*NW + gi;
            int cc_i = (int)cc; if (cc_i < 0) cc_i = 0; if (cc_i > NC-1) cc_i = NC-1;
            sH[tid]   = make_float4(3.f*(gx - 0.5f*gw), 3.f*(gx + 0.5f*gw),
                                    gy - 0.5f*gh, gy + 0.5f*gh);
            sNga[tid] = -(gw*gh);
            sC[tid]   = make_float4(gx - (float)gi, gy - (float)gj,
                                    __logf(__fdividef(gw, c_AW[bn])),
                                    __logf(__fdividef(gh, c_AH[bn])));
            sM[tid]   = sqrtf(2.f - w*h);
            int c = cell - base;
            if (c >= 0 && c < BLK) {
                atomicMax(&s_last[c], tid);
                if (cc_i < 32)      atomicOr(&s_cb0[c], 1u << cc_i);
                else if (cc_i < 64) atomicOr(&s_cb1[c], 1u << (cc_i - 32));
                else                atomicOr(&s_cb2[c], 1u << (cc_i - 64));
            }
        } else {
            sH[tid]   = make_float4(1e38f, -1e38f, 1e38f, -1e38f);
            sNga[tid] = -1e30f;                   // ga = +1e30 -> never passes prune
            if (tid < MAXB) {
                sC[tid] = make_float4(0.f, 0.f, 0.f, 0.f);
                sM[tid] = 0.f;
            }
        }
    }

    // ---- per-cell prologue (prefetched regs only; no shared reads) ----
    float s0a, s1a, paa, px1a, px2a, py1a, py2a;
    {
        float u0 = pexp(-L00), u1 = pexp(-L01);
        float d0 = 1.f + u0, d1 = 1.f + u1;
        float rr = __fdividef(1.f, d0*d1);          // single MUFU.RCP
        s0a = d1*rr; s1a = d0*rr;
        int hh = hw0 / NW, ww = hw0 - hh*NW;
        int aq = (b*3 + a0) >> 5;                   // faithful anchor-flatten quirk
        float pw = pexp(L02)*c_AW[aq], ph = pexp(L03)*c_AH[aq];
        float px = s0a + (float)ww, py = s1a + (float)hh;
        px1a = 3.f*(px - 0.5f*pw); px2a = 3.f*(px + 0.5f*pw);
        py1a = py - 0.5f*ph;       py2a = py + 0.5f*ph;
        paa = pw*ph;
    }

    // ---- block max of pred-box area (prune threshold) ----
    {
        float pm = v0 ? paa : 0.f;
#pragma unroll
        for (int off = 16; off; off >>= 1)
            pm = fmaxf(pm, __shfl_xor_sync(0xffffffffu, pm, off));
        if (lane == 0) s_pm[wid] = pm;
    }
    __syncthreads();   // covers phase-2 shared writes + s_pm

    // ---- warp 0: compact candidate gts (ga < 2*pa_max is necessary for ignore) ----
    if (wid == 0) {
        float pamax = 0.f;
#pragma unroll
        for (int j = 0; j < NWARPS; j++) pamax = fmaxf(pamax, s_pm[j]);
        float th = 2.f * pamax;
        float ng0 = sNga[lane];                      // slots 0..31
        bool  c0  = (-ng0) < th;
        bool  in1 = (lane + 32) < MAXB;              // slots 32..49
        float ng1 = in1 ? sNga[lane + 32] : -1e30f;
        bool  c1  = in1 && ((-ng1) < th);
        unsigned b0 = __ballot_sync(0xffffffffu, c0);
        unsigned b1 = __ballot_sync(0xffffffffu, c1);
        int n = __popc(b0) + __popc(b1);
        if (c0) { int p = __popc(b0 & ltm);              sHc[p] = sH[lane];      sNgac[p] = ng0; }
        if (c1) { int p = __popc(b0) + __popc(b1 & ltm); sHc[p] = sH[lane + 32]; sNgac[p] = ng1; }
        if (lane < 4) {                               // sentinel pad to next mult of 4
            sHc[n + lane]   = make_float4(1e38f, -1e38f, 1e38f, -1e38f);
            sNgac[n + lane] = -1e30f;
        }
        if (lane == 0) s_nc4 = (n + 3) >> 2;
    }
    __syncthreads();

    // ---- hot loop over compacted candidates only ----
    float dmax0 = -1e30f;
    int nc4 = s_nc4;
    for (int g4 = 0; g4 < nc4; g4++) {
#pragma unroll
        for (int j = 0; j < 4; j++) {
            float4 A  = sHc[g4*4 + j];
            float nga = sNgac[g4*4 + j];
            float cw = fmaxf(fminf(px2a, A.y) - fmaxf(px1a, A.x), 0.f);
            float ch = fmaxf(fminf(py2a, A.w) - fmaxf(py1a, A.z), 0.f);
            dmax0 = fmaxf(dmax0, fmaf(cw, ch, nga));   // 3*ca - ga
        }
    }
    bool ign0 = dmax0 > paa;       // 3*ca > pa + ga  <=>  iou > 0.5
    int last0 = s_last[tid];

    float coordL = 0.f, confL = 0.f, clsL = 0.f;

    // conf loss: merged-log.  obj: log(1+e^-c4);  back: c4 + log(1+e^-c4);  ign: 0
    {
        bool inc0 = v0 && (last0 >= 0 || !ign0);
        float t0 = inc0 ? (1.f + pexp(-L04)) : 1.f;
        if (inc0 && last0 < 0) confL += L04;
        confL += __logf(t0);
    }

    // ---- object-cell epilogue + queue append (warp-aggregated shared atomic) ----
    unsigned m0 = __ballot_sync(0xffffffffu, last0 >= 0);
    if (last0 >= 0) {
        float4 tc = sC[last0]; float m = sM[last0];
        float d0 = s0a*m - tc.x*m, d1 = s1a*m - tc.y*m;
        float d2 = L02*m - tc.z*m, d3 = L03*m - tc.w*m;
        coordL += 0.5f*(d0*d0 + d1*d1 + d2*d2 + d3*d3);
        int wbase = 0;
        int leader = __ffs(m0) - 1;
        if (lane == leader) wbase = atomicAdd(&s_qcnt, __popc(m0));
        wbase = __shfl_sync(m0, wbase, leader);   // mask = participating lanes ONLY
        int q = wbase + __popc(m0 & ltm);
        s_qoff[q] = off0;
        s_qb0[q] = s_cb0[tid]; s_qb1[q] = s_cb1[tid]; s_qb2[q] = s_cb2[tid];
    }
    __syncthreads();

    // ---- warp-cooperative class loss: 80 classes over 32 lanes, merged log ----
    int qn = s_qcnt;
    for (int e = wid; e < qn; e += NWARPS) {
        int basec = s_qoff[e] + 5*HW;
        unsigned cb0 = s_qb0[e], cb1 = s_qb1[e], cb2 = s_qb2[e];
        int c0i = lane, c1i = lane + 32, c2i = lane + 64;
        bool has2 = (c2i < NC);
        float xv0 = __ldg(out + basec + c0i*HW);
        float xv1 = __ldg(out + basec + c1i*HW);
        float xv2 = has2 ? __ldg(out + basec + c2i*HW) : 0.f;
        float t0 = 1.f + pexp(-xv0);
        float t1 = 1.f + pexp(-xv1);
        float t2 = has2 ? (1.f + pexp(-xv2)) : 1.f;
        clsL += __logf(t0 * t1 * t2);               // merged: one LG2 per 3 classes
        if (!((cb0 >> c0i) & 1u)) clsL += xv0;
        if (!((cb1 >> (c1i - 32)) & 1u)) clsL += xv1;
        if (has2 && !((cb2 >> (c2i - 64)) & 1u)) clsL += xv2;
    }

    // ---- block reduce 3 sums ----
    unsigned fm = 0xffffffffu;
#pragma unroll
    for (int off = 16; off; off >>= 1) {
        coordL += __shfl_down_sync(fm, coordL, off);
        confL  += __shfl_down_sync(fm, confL,  off);
        clsL   += __shfl_down_sync(fm, clsL,   off);
    }
    if (lane == 0) { s_red[0][wid] = coordL; s_red[1][wid] = confL; s_red[2][wid] = clsL; }
    __syncthreads();

    // ---- tid 0: global atomic accumulate + ticket + (last) finalize ----
    if (tid == 0) {
        float a0r = 0.f, a1r = 0.f, a2r = 0.f;
#pragma unroll
        for (int j = 0; j < NWARPS; j++) {
            a0r += s_red[0][j]; a1r += s_red[1][j]; a2r += s_red[2][j];
        }
        atomicAdd(&g_acc[0], a0r);
        atomicAdd(&g_acc[1], a1r);
        atomicAdd(&g_acc[2], a2r);
        __threadfence();
        int t = atomicAdd(&g_count, 1);
        if (t == NPART - 1) {
            volatile float* ga = g_acc;
            dout[0] = ga[0] / (float)NB;
            dout[1] = ga[1] / (float)NB;
            dout[2] = ga[2] / (float)NB;
            g_acc[0] = 0.f; g_acc[1] = 0.f; g_acc[2] = 0.f;   // reset for replay
            g_count = 0;
        }
    }
}

extern "C" void kernel_launch(void* const* d_in, const int* in_sizes, int n_in,
                              void* d_out, int out_size) {
    const float* output = (const float*)d_in[0];
    const float* target = (const float*)d_in[1];
    if (n_in >= 2 && in_sizes[0] == NB*MAXB*5) {  // defensive: inputs swapped
        output = (const float*)d_in[1];
        target = (const float*)d_in[0];
    }
    dim3 g(GXB, NB);
    kF<<<g, BLK>>>(output, target, (float*)d_out);
}